// round 7
// baseline (speedup 1.0000x reference)
#include <cuda_runtime.h>

#define IMG    512
#define SW     32          // strip width
#define SH     128         // strip height
#define NCH    4           // chunks per strip (SH/32)
#define BROWS  42          // hh rows (32 new + 10 carry)
#define ICOLS  42          // input cols incl. horizontal halo
#define PITCH  45          // input shared pitch (conflict-free H-pass reads)
#define HPITCH 33          // h-pass shared pitch (conflict-free V-pass reads)
#define NBLK   2048        // 16 * 4 * 32

#define C1 1.0e-4f
#define C2 9.0e-4f

__device__ float        g_partial[NBLK];
__device__ unsigned int g_count = 0;

__global__ __launch_bounds__(256) void ssim_strip_kernel(
    const float* __restrict__ pred,
    const float* __restrict__ target,
    float* __restrict__ out)
{
    __shared__ float w[11];
    __shared__ float sp[BROWS][PITCH];
    __shared__ float st[BROWS][PITCH];
    __shared__ float hh[5][BROWS][HPITCH];
    __shared__ float wsum[8];
    __shared__ int   s_last;

    const int tid = threadIdx.x;

    if (tid == 0) {
        float e[11];
        float s = 0.f;
        #pragma unroll
        for (int i = 0; i < 11; i++) {
            float d = (float)(i - 5);
            e[i] = __expf(-d * d / 4.5f);   // 2*sigma^2 = 4.5
            s += e[i];
        }
        float inv = 1.f / s;
        #pragma unroll
        for (int i = 0; i < 11; i++) w[i] = e[i] * inv;
    }

    const float* __restrict__ pimg = pred   + (size_t)blockIdx.z * IMG * IMG;
    const float* __restrict__ timg = target + (size_t)blockIdx.z * IMG * IMG;
    const int c0 = blockIdx.x * SW;
    const int r0 = blockIdx.y * SH;

    __syncthreads();          // weights visible
    float wr[11];
    #pragma unroll
    for (int i = 0; i < 11; i++) wr[i] = w[i];

    // static load decomposition: 8 threads per row, 6 col slots each
    const int lrow = tid >> 3;          // 0..31
    const int lcol = tid & 7;           // 0..7
    // V-pass mapping
    const int vj  = tid & 31;
    const int vi0 = (tid >> 5) * 4;

    float local = 0.f;

    // =================== prologue: chunk 0 =====================
    // load 42 rows (buffer row b <-> global row r0-5+b)
    #pragma unroll
    for (int pass = 0; pass < 2; pass++) {
        const int lr = lrow + 32 * pass;
        if (lr < BROWS) {
            const int gr = r0 - 5 + lr;
            const bool rok = ((unsigned)gr < IMG);
            const float* __restrict__ prow = pimg + gr * IMG;
            const float* __restrict__ trow = timg + gr * IMG;
            #pragma unroll
            for (int s = 0; s < 6; s++) {
                const int cc = lcol + 8 * s;
                if (cc < ICOLS) {
                    const int gc = c0 - 5 + cc;
                    float pv = 0.f, tv = 0.f;
                    if (rok && (unsigned)gc < IMG) {
                        float x = prow[gc];
                        pv = 1.f / (1.f + __expf(-x));
                        tv = trow[gc];
                    }
                    sp[lr][cc] = pv;
                    st[lr][cc] = tv;
                }
            }
        }
    }
    __syncthreads();

    // H-pass of all 42 rows: 336 tasks over 256 threads (2 ragged passes)
    #pragma unroll
    for (int pass = 0; pass < 2; pass++) {
        const int task = tid + 256 * pass;
        if (task < BROWS * 8) {
            const int r  = task >> 3;
            const int j0 = (task & 7) * 4;
            const float* __restrict__ pr = &sp[r][j0];
            const float* __restrict__ tr = &st[r][j0];
            float s0[4], s1[4], s2[4], s3[4], s4[4];
            #pragma unroll
            for (int u = 0; u < 4; u++) { s0[u]=0.f; s1[u]=0.f; s2[u]=0.f; s3[u]=0.f; s4[u]=0.f; }
            #pragma unroll
            for (int k = 0; k < 14; k++) {
                const float pa  = pr[k];
                const float pb  = tr[k];
                const float paa = pa * pa;
                const float pbb = pb * pb;
                const float pab = pa * pb;
                #pragma unroll
                for (int u = 0; u < 4; u++) {
                    if (k - u >= 0 && k - u <= 10) {
                        const float wk = wr[k - u];
                        s0[u] = fmaf(wk, pa,  s0[u]);
                        s1[u] = fmaf(wk, pb,  s1[u]);
                        s2[u] = fmaf(wk, paa, s2[u]);
                        s3[u] = fmaf(wk, pbb, s3[u]);
                        s4[u] = fmaf(wk, pab, s4[u]);
                    }
                }
            }
            #pragma unroll
            for (int u = 0; u < 4; u++) {
                hh[0][r][j0 + u] = s0[u];
                hh[1][r][j0 + u] = s1[u];
                hh[2][r][j0 + u] = s2[u];
                hh[3][r][j0 + u] = s3[u];
                hh[4][r][j0 + u] = s4[u];
            }
        }
    }
    __syncthreads();

    // =================== chunk loop =====================
    for (int ch = 0; ch < NCH; ch++) {
        // --- phase A: load chunk ch+1 inputs (overlaps V-pass latency) + V-pass(ch) ---
        if (ch < NCH - 1) {
            const int lr = lrow;
            const int gr = r0 + 32 * ch + 37 + lr;   // r0-5 + 32*(ch+1) + 10 + lr
            const bool rok = (gr < IMG);
            const float* __restrict__ prow = pimg + gr * IMG;
            const float* __restrict__ trow = timg + gr * IMG;
            #pragma unroll
            for (int s = 0; s < 6; s++) {
                const int cc = lcol + 8 * s;
                if (cc < ICOLS) {
                    const int gc = c0 - 5 + cc;
                    float pv = 0.f, tv = 0.f;
                    if (rok && (unsigned)gc < IMG) {
                        float x = prow[gc];
                        pv = 1.f / (1.f + __expf(-x));
                        tv = trow[gc];
                    }
                    sp[lr][cc] = pv;
                    st[lr][cc] = tv;
                }
            }
        }

        // V-pass(ch): field-major, register-staged
        {
            float acc[5][4];
            #pragma unroll
            for (int q = 0; q < 5; q++) {
                float v[14];
                #pragma unroll
                for (int k = 0; k < 14; k++) v[k] = hh[q][vi0 + k][vj];
                #pragma unroll
                for (int u = 0; u < 4; u++) {
                    float a = 0.f;
                    #pragma unroll
                    for (int k = 0; k < 11; k++) a = fmaf(wr[k], v[u + k], a);
                    acc[q][u] = a;
                }
            }
            #pragma unroll
            for (int u = 0; u < 4; u++) {
                const float mu1  = acc[0][u];
                const float mu2  = acc[1][u];
                const float mu1s = mu1 * mu1;
                const float mu2s = mu2 * mu2;
                const float mu12 = mu1 * mu2;
                const float sig1  = acc[2][u] - mu1s;
                const float sig2  = acc[3][u] - mu2s;
                const float sig12 = acc[4][u] - mu12;
                const float num = (2.f * mu12 + C1) * (2.f * sig12 + C2);
                const float den = (mu1s + mu2s + C1) * (sig1 + sig2 + C2);
                local += 1.f - __fdividef(num, den);
            }
        }
        __syncthreads();

        if (ch < NCH - 1) {
            // --- phase B: carry hh rows 32..41 -> 0..9 ---
            #pragma unroll
            for (int it = 0; it < 7; it++) {
                const int i = tid + 256 * it;
                if (i < 5 * 10 * SW) {
                    const int q  = i / 320;
                    const int t  = i - q * 320;
                    const int rr = t >> 5;
                    const int j  = t & 31;
                    hh[q][rr][j] = hh[q][32 + rr][j];
                }
            }
            __syncthreads();

            // --- phase C: H-pass of 32 new rows (sp row lr -> hh row 10+lr) ---
            {
                const int lr = tid >> 3;
                const int hr = 10 + lr;
                const int j0 = (tid & 7) * 4;
                const float* __restrict__ pr = &sp[lr][j0];
                const float* __restrict__ tr = &st[lr][j0];
                float s0[4], s1[4], s2[4], s3[4], s4[4];
                #pragma unroll
                for (int u = 0; u < 4; u++) { s0[u]=0.f; s1[u]=0.f; s2[u]=0.f; s3[u]=0.f; s4[u]=0.f; }
                #pragma unroll
                for (int k = 0; k < 14; k++) {
                    const float pa  = pr[k];
                    const float pb  = tr[k];
                    const float paa = pa * pa;
                    const float pbb = pb * pb;
                    const float pab = pa * pb;
                    #pragma unroll
                    for (int u = 0; u < 4; u++) {
                        if (k - u >= 0 && k - u <= 10) {
                            const float wk = wr[k - u];
                            s0[u] = fmaf(wk, pa,  s0[u]);
                            s1[u] = fmaf(wk, pb,  s1[u]);
                            s2[u] = fmaf(wk, paa, s2[u]);
                            s3[u] = fmaf(wk, pbb, s3[u]);
                            s4[u] = fmaf(wk, pab, s4[u]);
                        }
                    }
                }
                #pragma unroll
                for (int u = 0; u < 4; u++) {
                    hh[0][hr][j0 + u] = s0[u];
                    hh[1][hr][j0 + u] = s1[u];
                    hh[2][hr][j0 + u] = s2[u];
                    hh[3][hr][j0 + u] = s3[u];
                    hh[4][hr][j0 + u] = s4[u];
                }
            }
            __syncthreads();
        }
    }

    // ---- block reduction -> partial ----
    #pragma unroll
    for (int off = 16; off; off >>= 1)
        local += __shfl_down_sync(0xffffffffu, local, off);
    if ((tid & 31) == 0) wsum[tid >> 5] = local;
    __syncthreads();
    if (tid == 0) {
        float v = 0.f;
        #pragma unroll
        for (int i = 0; i < 8; i++) v += wsum[i];
        int blin = (blockIdx.z * 4 + blockIdx.y) * 16 + blockIdx.x;
        g_partial[blin] = v;
        __threadfence();
        unsigned old = atomicAdd(&g_count, 1u);
        s_last = (old == NBLK - 1) ? 1 : 0;
    }
    __syncthreads();

    // ---- last block: fixed-order final reduction (bit-deterministic) ----
    if (s_last) {
        __threadfence();
        float s = 0.f;
        #pragma unroll
        for (int j = 0; j < 8; j++) s += g_partial[tid + 256 * j];
        #pragma unroll
        for (int off = 16; off; off >>= 1)
            s += __shfl_down_sync(0xffffffffu, s, off);
        if ((tid & 31) == 0) wsum[tid >> 5] = s;
        __syncthreads();
        if (tid == 0) {
            float v = 0.f;
            #pragma unroll
            for (int i = 0; i < 8; i++) v += wsum[i];
            out[0] = v * (1.0f / 8388608.0f);   // / (32*512*512)
            g_count = 0;                        // reset for next graph replay
        }
    }
}

extern "C" void kernel_launch(void* const* d_in, const int* in_sizes, int n_in,
                              void* d_out, int out_size)
{
    const float* pred   = (const float*)d_in[0];
    const float* target = (const float*)d_in[1];
    dim3 grid(16, 4, 32);
    ssim_strip_kernel<<<grid, 256>>>(pred, target, (float*)d_out);
}

// round 9
// speedup vs baseline: 1.0411x; 1.0411x over previous
#include <cuda_runtime.h>

#define IMG    512
#define SW     32          // strip width
#define SH     256         // strip height
#define NCH    8           // chunks per strip (SH/32)
#define BROWS  42          // hh rows (32 new + 10 carry)
#define SROWS  32          // sp/st rows (steady-state input buffer)
#define ICOLS  42          // input cols incl. horizontal halo
#define PITCH  43          // input shared pitch (conflict-free H-pass reads)
#define HPITCH 32          // h-pass pitch: conflict-free V reads + aligned STS.128
#define NBLK   1024        // 16 * 2 * 32

#define C1 1.0e-4f
#define C2 9.0e-4f

__device__ float        g_partial[NBLK];
__device__ unsigned int g_count = 0;

__global__ __launch_bounds__(256, 5) void ssim_strip_kernel(
    const float* __restrict__ pred,
    const float* __restrict__ target,
    float* __restrict__ out)
{
    __shared__ float w[11];
    __shared__ __align__(16) float sp[SROWS][PITCH];
    __shared__ __align__(16) float st[SROWS][PITCH];
    __shared__ __align__(16) float hh[5][BROWS][HPITCH];
    __shared__ float wsum[8];
    __shared__ int   s_last;

    const int tid = threadIdx.x;

    if (tid == 0) {
        float e[11];
        float s = 0.f;
        #pragma unroll
        for (int i = 0; i < 11; i++) {
            float d = (float)(i - 5);
            e[i] = __expf(-d * d / 4.5f);   // 2*sigma^2 = 4.5
            s += e[i];
        }
        float inv = 1.f / s;
        #pragma unroll
        for (int i = 0; i < 11; i++) w[i] = e[i] * inv;
    }

    const float* __restrict__ pimg = pred   + (size_t)blockIdx.z * IMG * IMG;
    const float* __restrict__ timg = target + (size_t)blockIdx.z * IMG * IMG;
    const int c0 = blockIdx.x * SW;
    const int r0 = blockIdx.y * SH;

    __syncthreads();          // weights visible
    float wr[11];
    #pragma unroll
    for (int i = 0; i < 11; i++) wr[i] = w[i];

    // static decompositions
    const int lrow = tid >> 3;          // 0..31 (load & H-pass row)
    const int lcol = tid & 7;           // 0..7  (load col phase)
    const int hj0  = (tid & 7) * 4;     // H-pass output col base
    const int vj   = tid & 31;          // V-pass col
    const int vi0  = (tid >> 5) * 4;    // V-pass row base

    float local = 0.f;

#define LOAD_ROWS(GR_EXPR, DSTROW, ROWPRED)                                     \
    {                                                                           \
        const int gr = (GR_EXPR);                                               \
        const bool rok = (ROWPRED);                                             \
        const float* __restrict__ prow = pimg + gr * IMG;                       \
        const float* __restrict__ trow = timg + gr * IMG;                       \
        _Pragma("unroll")                                                       \
        for (int s = 0; s < 6; s++) {                                           \
            const int cc = lcol + 8 * s;                                        \
            if (cc < ICOLS) {                                                   \
                const int gc = c0 - 5 + cc;                                     \
                float pv = 0.f, tv = 0.f;                                       \
                if (rok && (unsigned)gc < IMG) {                                \
                    float x = prow[gc];                                         \
                    pv = 1.f / (1.f + __expf(-x));                              \
                    tv = trow[gc];                                              \
                }                                                               \
                sp[(DSTROW)][cc] = pv;                                          \
                st[(DSTROW)][cc] = tv;                                          \
            }                                                                   \
        }                                                                       \
    }

#define HPASS_ROW(SRCROW, DSTROW)                                               \
    {                                                                           \
        const float* __restrict__ pr = &sp[(SRCROW)][hj0];                      \
        const float* __restrict__ tr = &st[(SRCROW)][hj0];                      \
        float s0[4], s1[4], s2[4], s3[4], s4[4];                                \
        _Pragma("unroll")                                                       \
        for (int u = 0; u < 4; u++) { s0[u]=0.f; s1[u]=0.f; s2[u]=0.f; s3[u]=0.f; s4[u]=0.f; } \
        _Pragma("unroll")                                                       \
        for (int k = 0; k < 14; k++) {                                          \
            const float pa  = pr[k];                                            \
            const float pb  = tr[k];                                            \
            const float paa = pa * pa;                                          \
            const float pbb = pb * pb;                                          \
            const float pab = pa * pb;                                          \
            _Pragma("unroll")                                                   \
            for (int u = 0; u < 4; u++) {                                       \
                if (k - u >= 0 && k - u <= 10) {                                \
                    const float wk = wr[k - u];                                 \
                    s0[u] = fmaf(wk, pa,  s0[u]);                               \
                    s1[u] = fmaf(wk, pb,  s1[u]);                               \
                    s2[u] = fmaf(wk, paa, s2[u]);                               \
                    s3[u] = fmaf(wk, pbb, s3[u]);                               \
                    s4[u] = fmaf(wk, pab, s4[u]);                               \
                }                                                               \
            }                                                                   \
        }                                                                       \
        *(float4*)&hh[0][(DSTROW)][hj0] = make_float4(s0[0], s0[1], s0[2], s0[3]); \
        *(float4*)&hh[1][(DSTROW)][hj0] = make_float4(s1[0], s1[1], s1[2], s1[3]); \
        *(float4*)&hh[2][(DSTROW)][hj0] = make_float4(s2[0], s2[1], s2[2], s2[3]); \
        *(float4*)&hh[3][(DSTROW)][hj0] = make_float4(s3[0], s3[1], s3[2], s3[3]); \
        *(float4*)&hh[4][(DSTROW)][hj0] = make_float4(s4[0], s4[1], s4[2], s4[3]); \
    }

    // =================== prologue =====================
    // P1: input rows r0-5 .. r0+26 -> sp[0..31]   (gr may be <0 at by==0)
    LOAD_ROWS(r0 - 5 + lrow, lrow, ((unsigned)gr < IMG));
    __syncthreads();
    HPASS_ROW(lrow, lrow);                 // -> hh rows 0..31
    __syncthreads();
    // P2: input rows r0+27 .. r0+36 -> sp[0..9]   (gr <= 420, always in range)
    if (lrow < 10) LOAD_ROWS(r0 + 27 + lrow, lrow, true);
    __syncthreads();
    if (lrow < 10) HPASS_ROW(lrow, 32 + lrow);   // -> hh rows 32..41
    __syncthreads();

    // =================== chunk loop =====================
    for (int ch = 0; ch < NCH; ch++) {
        // ---- V-pass(ch): field-major, register-staged ----
        {
            float acc[5][4];
            #pragma unroll
            for (int q = 0; q < 5; q++) {
                float v[14];
                #pragma unroll
                for (int k = 0; k < 14; k++) v[k] = hh[q][vi0 + k][vj];
                #pragma unroll
                for (int u = 0; u < 4; u++) {
                    float a = 0.f;
                    #pragma unroll
                    for (int k = 0; k < 11; k++) a = fmaf(wr[k], v[u + k], a);
                    acc[q][u] = a;
                }
            }
            #pragma unroll
            for (int u = 0; u < 4; u++) {
                const float mu1  = acc[0][u];
                const float mu2  = acc[1][u];
                const float mu1s = mu1 * mu1;
                const float mu2s = mu2 * mu2;
                const float mu12 = mu1 * mu2;
                const float sig1  = acc[2][u] - mu1s;
                const float sig2  = acc[3][u] - mu2s;
                const float sig12 = acc[4][u] - mu12;
                const float num = (2.f * mu12 + C1) * (2.f * sig12 + C2);
                const float den = (mu1s + mu2s + C1) * (sig1 + sig2 + C2);
                local += 1.f - __fdividef(num, den);
            }
        }
        __syncthreads();

        if (ch < NCH - 1) {
            // ---- carry hh rows 32..41 -> 0..9 (float4) + load next 32 rows ----
            #pragma unroll
            for (int it = 0; it < 2; it++) {
                const int i = tid + 256 * it;          // 0..399 vec4 tasks
                if (i < 5 * 10 * (SW / 4)) {
                    const int q  = i / 80;
                    const int t  = i - q * 80;
                    const int rr = t >> 3;
                    const int jv = (t & 7) * 4;
                    *(float4*)&hh[q][rr][jv] = *(const float4*)&hh[q][32 + rr][jv];
                }
            }
            // input rows r0 + 32*ch + 37 + lrow  (can exceed IMG at strip end)
            LOAD_ROWS(r0 + 32 * ch + 37 + lrow, lrow, (gr < IMG));
            __syncthreads();

            // ---- H-pass 32 new rows -> hh[10..41] ----
            HPASS_ROW(lrow, 10 + lrow);
            __syncthreads();
        }
    }

    // ---- block reduction -> partial ----
    #pragma unroll
    for (int off = 16; off; off >>= 1)
        local += __shfl_down_sync(0xffffffffu, local, off);
    if ((tid & 31) == 0) wsum[tid >> 5] = local;
    __syncthreads();
    if (tid == 0) {
        float v = 0.f;
        #pragma unroll
        for (int i = 0; i < 8; i++) v += wsum[i];
        int blin = (blockIdx.z * 2 + blockIdx.y) * 16 + blockIdx.x;
        g_partial[blin] = v;
        __threadfence();
        unsigned old = atomicAdd(&g_count, 1u);
        s_last = (old == NBLK - 1) ? 1 : 0;
    }
    __syncthreads();

    // ---- last block: fixed-order final reduction (bit-deterministic) ----
    if (s_last) {
        __threadfence();
        float s = g_partial[tid] + g_partial[tid + 256]
                + g_partial[tid + 512] + g_partial[tid + 768];
        #pragma unroll
        for (int off = 16; off; off >>= 1)
            s += __shfl_down_sync(0xffffffffu, s, off);
        if ((tid & 31) == 0) wsum[tid >> 5] = s;
        __syncthreads();
        if (tid == 0) {
            float v = 0.f;
            #pragma unroll
            for (int i = 0; i < 8; i++) v += wsum[i];
            out[0] = v * (1.0f / 8388608.0f);   // / (32*512*512)
            g_count = 0;                        // reset for next graph replay
        }
    }
}

extern "C" void kernel_launch(void* const* d_in, const int* in_sizes, int n_in,
                              void* d_out, int out_size)
{
    const float* pred   = (const float*)d_in[0];
    const float* target = (const float*)d_in[1];
    dim3 grid(16, 2, 32);
    ssim_strip_kernel<<<grid, 256>>>(pred, target, (float*)d_out);
}

// round 11
// speedup vs baseline: 1.0793x; 1.0367x over previous
#include <cuda_runtime.h>

#define IMG    512
#define SW     32          // strip width
#define SH     256         // strip height
#define NCH    8           // chunks per strip (SH/32)
#define BROWS  42          // hh rows (32 new + 10 carry)
#define SROWS  32          // sp/st rows (input buffer)
#define ICOLS  42          // input cols incl. horizontal halo
#define PITCH  44          // input pitch: 16B-aligned rows, conflict-free LDS.128
#define HPITCH 32          // h-pass pitch: conflict-free V reads + aligned STS.128
#define NBLK   1024        // 16 * 2 * 32

#define C1 1.0e-4f
#define C2 9.0e-4f

// Gaussian(sigma=1.5, k=11) weights as literals (match runtime fp32 to ~1e-7;
// loss tolerance is 1e-3). Enables FFMA-imm (rt=1 vs rt=2 for 3-reg FFMA).
#define WLIT(k) ((k)==0 ? 0.00102838f : (k)==1 ? 0.00759876f : (k)==2 ? 0.03600077f : \
                 (k)==3 ? 0.10936069f : (k)==4 ? 0.21300554f : (k)==5 ? 0.26601172f : \
                 (k)==6 ? 0.21300554f : (k)==7 ? 0.10936069f : (k)==8 ? 0.03600077f : \
                 (k)==9 ? 0.00759876f : 0.00102838f)

__device__ float        g_partial[NBLK];
__device__ unsigned int g_count = 0;

__global__ __launch_bounds__(256, 5) void ssim_strip_kernel(
    const float* __restrict__ pred,
    const float* __restrict__ target,
    float* __restrict__ out)
{
    __shared__ __align__(16) float sp[SROWS][PITCH];
    __shared__ __align__(16) float st[SROWS][PITCH];
    __shared__ __align__(16) float hh[5][BROWS][HPITCH];
    __shared__ float wsum[8];
    __shared__ int   s_last;

    const int tid = threadIdx.x;

    const float* __restrict__ pimg = pred   + (size_t)blockIdx.z * IMG * IMG;
    const float* __restrict__ timg = target + (size_t)blockIdx.z * IMG * IMG;
    const int c0 = blockIdx.x * SW;
    const int r0 = blockIdx.y * SH;

    // static decompositions
    const int lrow = tid >> 3;          // 0..31 (load & H-pass row)
    const int lcol = tid & 7;           // 0..7  (load col phase)
    const int hj0  = (tid & 7) * 4;     // H-pass output col base
    const int vj   = tid & 31;          // V-pass col
    const int vi0  = (tid >> 5) * 4;    // V-pass row base

    float local = 0.f;

#define LOAD_ROWS(GR_EXPR, DSTROW, ROWPRED)                                     \
    {                                                                           \
        const int gr = (GR_EXPR);                                               \
        const bool rok = (ROWPRED);                                             \
        const float* __restrict__ prow = pimg + gr * IMG;                       \
        const float* __restrict__ trow = timg + gr * IMG;                       \
        _Pragma("unroll")                                                       \
        for (int s = 0; s < 6; s++) {                                           \
            const int cc = lcol + 8 * s;                                        \
            if (cc < ICOLS) {                                                   \
                const int gc = c0 - 5 + cc;                                     \
                float pv = 0.f, tv = 0.f;                                       \
                if (rok && (unsigned)gc < IMG) {                                \
                    float x = prow[gc];                                         \
                    pv = 1.f / (1.f + __expf(-x));                              \
                    tv = trow[gc];                                              \
                }                                                               \
                sp[(DSTROW)][cc] = pv;                                          \
                st[(DSTROW)][cc] = tv;                                          \
            }                                                                   \
        }                                                                       \
    }

#define HPASS_ROW(SRCROW, DSTROW)                                               \
    {                                                                           \
        const float4* __restrict__ pr4 = (const float4*)&sp[(SRCROW)][hj0];     \
        const float4* __restrict__ tr4 = (const float4*)&st[(SRCROW)][hj0];     \
        float av[16], bv[16];                                                   \
        _Pragma("unroll")                                                       \
        for (int i = 0; i < 4; i++) {                                           \
            const float4 a4 = pr4[i];                                           \
            const float4 b4 = tr4[i];                                           \
            av[4*i+0] = a4.x; av[4*i+1] = a4.y; av[4*i+2] = a4.z; av[4*i+3] = a4.w; \
            bv[4*i+0] = b4.x; bv[4*i+1] = b4.y; bv[4*i+2] = b4.z; bv[4*i+3] = b4.w; \
        }                                                                       \
        float s0[4], s1[4], s2[4], s3[4], s4[4];                                \
        _Pragma("unroll")                                                       \
        for (int u = 0; u < 4; u++) { s0[u]=0.f; s1[u]=0.f; s2[u]=0.f; s3[u]=0.f; s4[u]=0.f; } \
        _Pragma("unroll")                                                       \
        for (int k = 0; k < 14; k++) {                                          \
            const float pa  = av[k];                                            \
            const float pb  = bv[k];                                            \
            const float paa = pa * pa;                                          \
            const float pbb = pb * pb;                                          \
            const float pab = pa * pb;                                          \
            _Pragma("unroll")                                                   \
            for (int u = 0; u < 4; u++) {                                       \
                if (k - u >= 0 && k - u <= 10) {                                \
                    const float wk = WLIT(k - u);                               \
                    s0[u] = fmaf(wk, pa,  s0[u]);                               \
                    s1[u] = fmaf(wk, pb,  s1[u]);                               \
                    s2[u] = fmaf(wk, paa, s2[u]);                               \
                    s3[u] = fmaf(wk, pbb, s3[u]);                               \
                    s4[u] = fmaf(wk, pab, s4[u]);                               \
                }                                                               \
            }                                                                   \
        }                                                                       \
        *(float4*)&hh[0][(DSTROW)][hj0] = make_float4(s0[0], s0[1], s0[2], s0[3]); \
        *(float4*)&hh[1][(DSTROW)][hj0] = make_float4(s1[0], s1[1], s1[2], s1[3]); \
        *(float4*)&hh[2][(DSTROW)][hj0] = make_float4(s2[0], s2[1], s2[2], s2[3]); \
        *(float4*)&hh[3][(DSTROW)][hj0] = make_float4(s3[0], s3[1], s3[2], s3[3]); \
        *(float4*)&hh[4][(DSTROW)][hj0] = make_float4(s4[0], s4[1], s4[2], s4[3]); \
    }

    // =================== prologue =====================
    // P1: input rows r0-5 .. r0+26 -> sp[0..31]   (gr may be <0 at by==0)
    LOAD_ROWS(r0 - 5 + lrow, lrow, ((unsigned)gr < IMG));
    __syncthreads();
    HPASS_ROW(lrow, lrow);                 // -> hh rows 0..31
    __syncthreads();
    // P2: input rows r0+27 .. r0+36 -> sp[0..9]   (always in range)
    if (lrow < 10) LOAD_ROWS(r0 + 27 + lrow, lrow, true);
    __syncthreads();
    if (lrow < 10) HPASS_ROW(lrow, 32 + lrow);   // -> hh rows 32..41
    __syncthreads();

    // =================== chunk loop =====================
    for (int ch = 0; ch < NCH; ch++) {
        // ---- V-pass(ch): field-major, register-staged, FFMA-imm ----
        {
            float acc[5][4];
            #pragma unroll
            for (int q = 0; q < 5; q++) {
                float v[14];
                #pragma unroll
                for (int k = 0; k < 14; k++) v[k] = hh[q][vi0 + k][vj];
                #pragma unroll
                for (int u = 0; u < 4; u++) {
                    float a = 0.f;
                    #pragma unroll
                    for (int k = 0; k < 11; k++) a = fmaf(WLIT(k), v[u + k], a);
                    acc[q][u] = a;
                }
            }
            #pragma unroll
            for (int u = 0; u < 4; u++) {
                const float mu1  = acc[0][u];
                const float mu2  = acc[1][u];
                const float mu1s = mu1 * mu1;
                const float mu2s = mu2 * mu2;
                const float mu12 = mu1 * mu2;
                const float sig1  = acc[2][u] - mu1s;
                const float sig2  = acc[3][u] - mu2s;
                const float sig12 = acc[4][u] - mu12;
                const float num = (2.f * mu12 + C1) * (2.f * sig12 + C2);
                const float den = (mu1s + mu2s + C1) * (sig1 + sig2 + C2);
                local += 1.f - __fdividef(num, den);
            }
        }
        __syncthreads();

        if (ch < NCH - 1) {
            // ---- carry hh rows 32..41 -> 0..9 (float4) + load next 32 rows ----
            #pragma unroll
            for (int it = 0; it < 2; it++) {
                const int i = tid + 256 * it;          // 0..399 vec4 tasks
                if (i < 5 * 10 * (SW / 4)) {
                    const int q  = i / 80;
                    const int t  = i - q * 80;
                    const int rr = t >> 3;
                    const int jv = (t & 7) * 4;
                    *(float4*)&hh[q][rr][jv] = *(const float4*)&hh[q][32 + rr][jv];
                }
            }
            // input rows r0 + 32*ch + 37 + lrow (can exceed IMG at strip end)
            LOAD_ROWS(r0 + 32 * ch + 37 + lrow, lrow, (gr < IMG));
            __syncthreads();

            // ---- H-pass 32 new rows -> hh[10..41] ----
            HPASS_ROW(lrow, 10 + lrow);
            __syncthreads();
        }
    }

    // ---- block reduction -> partial ----
    #pragma unroll
    for (int off = 16; off; off >>= 1)
        local += __shfl_down_sync(0xffffffffu, local, off);
    if ((tid & 31) == 0) wsum[tid >> 5] = local;
    __syncthreads();
    if (tid == 0) {
        float v = 0.f;
        #pragma unroll
        for (int i = 0; i < 8; i++) v += wsum[i];
        int blin = (blockIdx.z * 2 + blockIdx.y) * 16 + blockIdx.x;
        g_partial[blin] = v;
        __threadfence();
        unsigned old = atomicAdd(&g_count, 1u);
        s_last = (old == NBLK - 1) ? 1 : 0;
    }
    __syncthreads();

    // ---- last block: fixed-order final reduction (bit-deterministic) ----
    if (s_last) {
        __threadfence();
        float s = g_partial[tid] + g_partial[tid + 256]
                + g_partial[tid + 512] + g_partial[tid + 768];
        #pragma unroll
        for (int off = 16; off; off >>= 1)
            s += __shfl_down_sync(0xffffffffu, s, off);
        if ((tid & 31) == 0) wsum[tid >> 5] = s;
        __syncthreads();
        if (tid == 0) {
            float v = 0.f;
            #pragma unroll
            for (int i = 0; i < 8; i++) v += wsum[i];
            out[0] = v * (1.0f / 8388608.0f);   // / (32*512*512)
            g_count = 0;                        // reset for next graph replay
        }
    }
}

extern "C" void kernel_launch(void* const* d_in, const int* in_sizes, int n_in,
                              void* d_out, int out_size)
{
    const float* pred   = (const float*)d_in[0];
    const float* target = (const float*)d_in[1];
    dim3 grid(16, 2, 32);
    ssim_strip_kernel<<<grid, 256>>>(pred, target, (float*)d_out);
}